// round 12
// baseline (speedup 1.0000x reference)
#include <cuda_runtime.h>
#include <cuda_bf16.h>
#include <cstdint>

#define THREADS 128
#define HID 100
#define NC 30
#define SD 10
#define BETA_F 3.0f
#define MAXA_F 5.0f

// ---- precomputed mma B fragments (uint4 = hi b0,b1, lo b0,b1) ----
#define NFRAG2_LOC (7 * 8 * 32)    // layer2 loc: 7 k-chunks x 8 n-tiles x 32 lanes
#define NFRAG2_VAL (7 * 4 * 32)    // layer2 val
#define NFRAG1     (13 * 32)       // layer1 (per branch): 13 n-tiles x 32 lanes
#define NFRAG_TOT  (NFRAG2_LOC + NFRAG2_VAL + 2 * NFRAG1)
__device__ uint4 d_bfrag[NFRAG_TOT];

// ---- SMEM: ew relay only (per warp: 16 rows x 44 floats, conflict-free) ----
#define EW_STRIDE 44
#define SMEM_BYTES (4 * 16 * EW_STRIDE * 4)   // 11264 B

__device__ __forceinline__ float tanh_fast(float x) {
    float e = __expf(2.0f * x);
    return 1.0f - __fdividef(2.0f, e + 1.0f);
}
__device__ __forceinline__ void mma_bf16(float* c, const uint32_t* A,
                                         uint32_t b0, uint32_t b1) {
    asm volatile(
        "mma.sync.aligned.m16n8k16.row.col.f32.bf16.bf16.f32 "
        "{%0,%1,%2,%3}, {%4,%5,%6,%7}, {%8,%9}, {%0,%1,%2,%3};"
        : "+f"(c[0]), "+f"(c[1]), "+f"(c[2]), "+f"(c[3])
        : "r"(A[0]), "r"(A[1]), "r"(A[2]), "r"(A[3]), "r"(b0), "r"(b1));
}
// 3-term split mma: hi*hi + hi*lo + lo*hi
__device__ __forceinline__ void mma3(float* c, const uint32_t* Ah,
                                     const uint32_t* Al, uint4 b) {
    mma_bf16(c, Ah, b.x, b.y);
    mma_bf16(c, Ah, b.z, b.w);
    mma_bf16(c, Al, b.x, b.y);
}
__device__ __forceinline__ uint32_t cvt2(float hi, float lo) {
    uint32_t r;
    asm("cvt.rn.bf16x2.f32 %0, %1, %2;" : "=r"(r) : "f"(hi), "f"(lo));
    return r;
}
// split (vx, vy) -> (hi bf16x2, lo bf16x2)
__device__ __forceinline__ void split2(float vx, float vy, uint32_t& h, uint32_t& l) {
    h = cvt2(vy, vx);
    float lx = vx - __uint_as_float(h << 16);
    float ly = vy - __uint_as_float(h & 0xFFFF0000u);
    l = cvt2(ly, lx);
}

// ---- prep: build all B fragments in mma lane order ----
// layer2 frags carry ONLY weights (bias added in epilogue).
extern "C" __global__ void prep_kernel(const float* __restrict__ W1,
                                       const float* __restrict__ b1,
                                       const float* __restrict__ W2,
                                       const float* __restrict__ L1,
                                       const float* __restrict__ bl1,
                                       const float* __restrict__ WL2) {
    int t = blockIdx.x * blockDim.x + threadIdx.x;
    int stride = gridDim.x * blockDim.x;
    for (int idx = t; idx < NFRAG_TOT; idx += stride) {
        float v[4];
        if (idx < NFRAG2_LOC + NFRAG2_VAL) {            // ---- layer2 frags ----
            bool isloc = idx < NFRAG2_LOC;
            int rel = isloc ? idx : idx - NFRAG2_LOC;
            int lane = rel & 31;
            int f = rel >> 5;
            int nt = isloc ? 8 : 4;
            int q = f / nt, tn = f % nt;
            int k0 = q * 16 + 2 * (lane & 3);
            int n  = tn * 8 + (lane >> 2);
            #pragma unroll
            for (int e = 0; e < 4; e++) {
                int k = k0 + (e >> 1) * 8 + (e & 1);
                float x = 0.0f;
                if (isloc) {
                    if (n < 60 && k < HID) x = WL2[(n >> 1) * 200 + k * 2 + (n & 1)];
                } else {
                    if (n < NC && k < HID) x = W2[k * NC + n];
                }
                v[e] = x;
            }
        } else {                                        // ---- layer1 frags ----
            int rel = idx - (NFRAG2_LOC + NFRAG2_VAL);
            bool isloc = rel < NFRAG1;
            if (!isloc) rel -= NFRAG1;
            int lane = rel & 31;
            int tn = rel >> 5;                          // 0..12
            int k0 = 2 * (lane & 3);
            int n  = tn * 8 + (lane >> 2);              // hidden unit j
            const float* Wm = isloc ? L1 : W1;
            const float* bm = isloc ? bl1 : b1;
            #pragma unroll
            for (int e = 0; e < 4; e++) {
                int k = k0 + (e >> 1) * 8 + (e & 1);
                float x = 0.0f;
                if (n < HID) {
                    if (k < SD)       x = Wm[k * HID + n];
                    else if (k == SD) x = bm[n];        // layer1 bias via s ones-col
                }
                v[e] = x;
            }
        }
        unsigned short hb[4], lb[4];
        #pragma unroll
        for (int e = 0; e < 4; e++) {
            __nv_bfloat16 h = __float2bfloat16(v[e]);
            hb[e] = __bfloat16_as_ushort(h);
            lb[e] = __bfloat16_as_ushort(__float2bfloat16(v[e] - __bfloat162float(h)));
        }
        uint4 o;
        o.x = (uint32_t)hb[0] | ((uint32_t)hb[1] << 16);
        o.y = (uint32_t)hb[2] | ((uint32_t)hb[3] << 16);
        o.z = (uint32_t)lb[0] | ((uint32_t)lb[1] << 16);
        o.w = (uint32_t)lb[2] | ((uint32_t)lb[3] << 16);
        d_bfrag[idx] = o;
    }
}

// per-thread row data for one 16-row tile (2 rows: lr, lr+8)
struct RD {
    float2 v01[2];   // s cols 2lq, 2lq+1
    float2 v23[2];   // s cols 8,9 (lq==0 lanes only)
    float2 av[2];    // action
};

__device__ __forceinline__ RD load_rows(const float* __restrict__ s,
                                        const float* __restrict__ a,
                                        int base, int lr, int lq, int B) {
    RD rd;
    #pragma unroll
    for (int rr = 0; rr < 2; rr++) {
        int r = base + lr + rr * 8;
        r = r < B ? r : B - 1;
        const float* sr = s + (size_t)r * SD;
        rd.v01[rr] = __ldg((const float2*)(sr + 2 * lq));
        if (lq == 0) rd.v23[rr] = __ldg((const float2*)(sr + 8));
        rd.av[rr] = __ldg((const float2*)(a + (size_t)r * 2));
    }
    return rd;
}

// one branch, 16 rows/warp: layer1 (tensor) -> register relu/split -> layer2
// Rolling prefetch: layer2 frags 2 tiles ahead; next-q layer1 frags during layer2.
template<int NT>
__device__ __forceinline__ void branch_gemm(
    const uint4* __restrict__ bf1, const uint4* __restrict__ bf2,
    const uint32_t (&Ash)[4], const uint32_t (&Asl)[4],
    int lane, float (&c)[NT][4])
{
    #pragma unroll
    for (int tn = 0; tn < NT; tn++)
        #pragma unroll
        for (int e = 0; e < 4; e++) c[tn][e] = 0.0f;

    uint4 b1a = __ldg(&bf1[0 * 32 + lane]);
    uint4 b1b = __ldg(&bf1[1 * 32 + lane]);

    #pragma unroll
    for (int q = 0; q < 7; q++) {
        uint4 bb[NT];
        bb[0] = __ldg(&bf2[(q * NT + 0) * 32 + lane]);
        bb[1] = __ldg(&bf2[(q * NT + 1) * 32 + lane]);

        // ---- layer1: hidden cols [16q, 16q+16) ----
        float C[2][4];
        #pragma unroll
        for (int h = 0; h < 2; h++)
            #pragma unroll
            for (int e = 0; e < 4; e++) C[h][e] = 0.0f;
        mma3(C[0], Ash, Asl, b1a);
        if (q < 6) mma3(C[1], Ash, Asl, b1b);   // q==6: tile 13 absent -> h=0

        // ---- relu + split -> layer2 A fragments (registers only) ----
        uint32_t Ah[4], Al[4];
        #pragma unroll
        for (int h = 0; h < 2; h++) {
            float v0 = fmaxf(C[h][0], 0.0f);
            float v1 = fmaxf(C[h][1], 0.0f);
            float v2 = fmaxf(C[h][2], 0.0f);
            float v3 = fmaxf(C[h][3], 0.0f);
            split2(v0, v1, Ah[2 * h + 0], Al[2 * h + 0]);   // row lr
            split2(v2, v3, Ah[2 * h + 1], Al[2 * h + 1]);   // row lr+8
        }

        // ---- layer2 with rolling prefetch ----
        #pragma unroll
        for (int tn = 0; tn < NT; tn++) {
            if (tn == 0 && q < 6) b1a = __ldg(&bf1[(2 * q + 2) * 32 + lane]);
            if (tn == 1 && q < 5) b1b = __ldg(&bf1[(2 * q + 3) * 32 + lane]);
            if (tn + 2 < NT) bb[tn + 2] = __ldg(&bf2[(q * NT + tn + 2) * 32 + lane]);
            mma3(c[tn], Ah, Al, bb[tn]);
        }
    }
}

extern "C" __global__ void __launch_bounds__(THREADS, 6)
net_kernel(const float* __restrict__ s, const float* __restrict__ a,
           const float* __restrict__ b2, const float* __restrict__ bL2,
           float* __restrict__ out, int B, int ntiles)
{
    extern __shared__ __align__(16) float ews[];
    const int t = threadIdx.x;
    const int lane = t & 31;
    const int warp = t >> 5;
    const int lq = lane & 3, lr = lane >> 2;
    float* ewp = ews + warp * (16 * EW_STRIDE);

    const uint4* bf2_loc = d_bfrag;
    const uint4* bf2_val = d_bfrag + NFRAG2_LOC;
    const uint4* bf1_loc = d_bfrag + NFRAG2_LOC + NFRAG2_VAL;
    const uint4* bf1_val = bf1_loc + NFRAG1;

    int tile = blockIdx.x;
    if (tile >= ntiles) return;
    RD rd = load_rows(s, a, tile * 64 + warp * 16, lr, lq, B);

    while (true) {
        const int base = tile * 64 + warp * 16;

        // ---- A fragments of s (K=16: 10 inputs + ones col @10 for l1 bias) ----
        uint32_t Ash[4], Asl[4];
        #pragma unroll
        for (int rr = 0; rr < 2; rr++) {
            float2 v23;
            if (lq == 0)      v23 = rd.v23[rr];
            else if (lq == 1) v23 = make_float2(1.0f, 0.0f);   // ones col @10
            else              v23 = make_float2(0.0f, 0.0f);
            split2(rd.v01[rr].x, rd.v01[rr].y, Ash[rr],     Asl[rr]);
            split2(v23.x,        v23.y,        Ash[2 + rr], Asl[2 + rr]);
        }
        const float2 av0 = rd.av[0];
        const float2 av1 = rd.av[1];

        // ---- prefetch next tile's rows (hidden under both GEMMs) ----
        const int tnext = tile + gridDim.x;
        const bool has_next = tnext < ntiles;
        if (has_next) rd = load_rows(s, a, tnext * 64 + warp * 16, lr, lq, B);

        // ---- loc branch: 30 centroid (x,y) pairs in N=64 ----
        float cl[8][4];
        branch_gemm<8>(bf1_loc, bf2_loc, Ash, Asl, lane, cl);

        // ---- loc epilogue: +bias, centroids -> ew (SMEM relay) + den ----
        float den0 = 0.0f, den1 = 0.0f;
        #pragma unroll
        for (int tn = 0; tn < 8; tn++) {
            int n = tn * 4 + lq;
            float e0 = 0.0f, e1 = 0.0f;
            if (n < NC) {
                float2 bl = __ldg((const float2*)(bL2 + 2 * n));
                float px = MAXA_F * tanh_fast(cl[tn][0] + bl.x);
                float py = MAXA_F * tanh_fast(cl[tn][1] + bl.y);
                float dx = px - av0.x, dy = py - av0.y;
                e0 = __expf(-BETA_F * sqrtf(fmaf(dx, dx, dy * dy)));
                px = MAXA_F * tanh_fast(cl[tn][2] + bl.x);
                py = MAXA_F * tanh_fast(cl[tn][3] + bl.y);
                dx = px - av1.x; dy = py - av1.y;
                e1 = __expf(-BETA_F * sqrtf(fmaf(dx, dx, dy * dy)));
            }
            ewp[lr * EW_STRIDE + n]       = e0;
            ewp[(lr + 8) * EW_STRIDE + n] = e1;
            den0 += e0;
            den1 += e1;
        }
        den0 += __shfl_xor_sync(0xFFFFFFFFu, den0, 1);
        den0 += __shfl_xor_sync(0xFFFFFFFFu, den0, 2);
        den1 += __shfl_xor_sync(0xFFFFFFFFu, den1, 1);
        den1 += __shfl_xor_sync(0xFFFFFFFFu, den1, 2);
        __syncwarp();

        // ---- val branch: 30 values in N=32 ----
        float cv[4][4];
        branch_gemm<4>(bf1_val, bf2_val, Ash, Asl, lane, cv);

        // ---- val epilogue: num = sum ew*(v + bias) ----
        float num0 = 0.0f, num1 = 0.0f;
        #pragma unroll
        for (int tv = 0; tv < 4; tv++) {
            int n0 = tv * 8 + 2 * lq;
            float2 bb = (n0 < NC) ? __ldg((const float2*)(b2 + n0))
                                  : make_float2(0.0f, 0.0f);
            float2 e0 = *(float2*)(ewp + lr * EW_STRIDE + n0);
            float2 e1 = *(float2*)(ewp + (lr + 8) * EW_STRIDE + n0);
            num0 += (cv[tv][0] + bb.x) * e0.x + (cv[tv][1] + bb.y) * e0.y;
            num1 += (cv[tv][2] + bb.x) * e1.x + (cv[tv][3] + bb.y) * e1.y;
        }
        num0 += __shfl_xor_sync(0xFFFFFFFFu, num0, 1);
        num0 += __shfl_xor_sync(0xFFFFFFFFu, num0, 2);
        num1 += __shfl_xor_sync(0xFFFFFFFFu, num1, 1);
        num1 += __shfl_xor_sync(0xFFFFFFFFu, num1, 2);
        if (lq == 0) {
            int r0 = base + lr, r1 = base + lr + 8;
            if (r0 < B) out[r0] = num0 / den0;
            if (r1 < B) out[r1] = num1 / den1;
        }
        __syncwarp();     // protect ew relay before next iteration overwrites

        if (!has_next) break;
        tile = tnext;
    }
}

extern "C" void kernel_launch(void* const* d_in, const int* in_sizes, int n_in,
                              void* d_out, int out_size) {
    const float* s   = (const float*)d_in[0];
    const float* a   = (const float*)d_in[1];
    const float* W1  = (const float*)d_in[2];
    const float* b1  = (const float*)d_in[3];
    const float* W2  = (const float*)d_in[4];
    const float* b2  = (const float*)d_in[5];
    const float* L1  = (const float*)d_in[6];
    const float* bl1 = (const float*)d_in[7];
    const float* WL2 = (const float*)d_in[8];
    const float* bL2 = (const float*)d_in[9];
    float* out = (float*)d_out;

    const int B = in_sizes[0] / SD;
    const int ntiles = (B + 63) / 64;
    const int grid = ntiles < 888 ? ntiles : 888;   // 148 SMs x 6 CTAs

    prep_kernel<<<8, 256>>>(W1, b1, W2, L1, bl1, WL2);

    net_kernel<<<grid, THREADS, SMEM_BYTES>>>(s, a, b2, bL2, out, B, ntiles);
}

// round 13
// speedup vs baseline: 1.1647x; 1.1647x over previous
#include <cuda_runtime.h>
#include <cuda_bf16.h>
#include <cstdint>

#define THREADS 128
#define HID 100
#define NC 30
#define SD 10
#define BETA_F 3.0f
#define MAXA_F 5.0f

// ---- precomputed mma B fragments (uint4 = hi b0,b1, lo b0,b1) ----
#define NFRAG2_LOC (7 * 8 * 32)    // layer2 loc: 7 k-chunks x 8 n-tiles x 32 lanes
#define NFRAG2_VAL (7 * 4 * 32)    // layer2 val (columns PERMUTED, see prep)
#define NFRAG1     (13 * 32)       // layer1 (per branch): 13 n-tiles x 32 lanes
#define NFRAG_TOT  (NFRAG2_LOC + NFRAG2_VAL + 2 * NFRAG1)
__device__ uint4 d_bfrag[NFRAG_TOT];

__device__ __forceinline__ float tanh_fast(float x) {
    float e = __expf(2.0f * x);
    return 1.0f - __fdividef(2.0f, e + 1.0f);
}
__device__ __forceinline__ void mma_bf16(float* c, const uint32_t* A,
                                         uint32_t b0, uint32_t b1) {
    asm volatile(
        "mma.sync.aligned.m16n8k16.row.col.f32.bf16.bf16.f32 "
        "{%0,%1,%2,%3}, {%4,%5,%6,%7}, {%8,%9}, {%0,%1,%2,%3};"
        : "+f"(c[0]), "+f"(c[1]), "+f"(c[2]), "+f"(c[3])
        : "r"(A[0]), "r"(A[1]), "r"(A[2]), "r"(A[3]), "r"(b0), "r"(b1));
}
__device__ __forceinline__ uint32_t cvt2(float hi, float lo) {
    uint32_t r;
    asm("cvt.rn.bf16x2.f32 %0, %1, %2;" : "=r"(r) : "f"(hi), "f"(lo));
    return r;
}
// split (vx, vy) -> (hi bf16x2, lo bf16x2)
__device__ __forceinline__ void split2(float vx, float vy, uint32_t& h, uint32_t& l) {
    h = cvt2(vy, vx);
    float lx = vx - __uint_as_float(h << 16);
    float ly = vy - __uint_as_float(h & 0xFFFF0000u);
    l = cvt2(ly, lx);
}

// ---- prep: build all B fragments in mma lane order ----
// Val layer2 columns are PERMUTED so that the val C-fragment's lane ownership
// matches the loc C-fragment's centroid ownership:
//   tile position p (=col within 8-wide tile, p = 2*lq + e)  carries
//   centroid n = 8*tv + 4*(p&1) + (p>>1)   (bijective per tile)
// => lane lq's cv[tv][e] is the value of centroid n = 4*(2tv+e) + lq, which is
//    exactly the centroid whose ew lane lq computed in the loc epilogue.
extern "C" __global__ void prep_kernel(const float* __restrict__ W1,
                                       const float* __restrict__ b1,
                                       const float* __restrict__ W2,
                                       const float* __restrict__ b2,
                                       const float* __restrict__ L1,
                                       const float* __restrict__ bl1,
                                       const float* __restrict__ WL2,
                                       const float* __restrict__ bL2) {
    int t = blockIdx.x * blockDim.x + threadIdx.x;
    int stride = gridDim.x * blockDim.x;
    for (int idx = t; idx < NFRAG_TOT; idx += stride) {
        float v[4];
        if (idx < NFRAG2_LOC + NFRAG2_VAL) {            // ---- layer2 frags ----
            bool isloc = idx < NFRAG2_LOC;
            int rel = isloc ? idx : idx - NFRAG2_LOC;
            int lane = rel & 31;
            int f = rel >> 5;
            int nt = isloc ? 8 : 4;
            int q = f / nt, tn = f % nt;
            int k0 = q * 16 + 2 * (lane & 3);
            int n;
            if (isloc) {
                n = tn * 8 + (lane >> 2);               // natural order
            } else {
                int p = lane >> 2;                      // col position in tile
                n = tn * 8 + 4 * (p & 1) + (p >> 1);    // permuted centroid idx
            }
            #pragma unroll
            for (int e = 0; e < 4; e++) {
                int k = k0 + (e >> 1) * 8 + (e & 1);
                float x = 0.0f;
                if (isloc) {
                    if (n < 60) {
                        if (k < HID)       x = WL2[(n >> 1) * 200 + k * 2 + (n & 1)];
                        else if (k == HID) x = bL2[n];
                    }
                } else {
                    if (n < NC) {
                        if (k < HID)       x = W2[k * NC + n];
                        else if (k == HID) x = b2[n];
                    }
                }
                v[e] = x;
            }
        } else {                                        // ---- layer1 frags ----
            int rel = idx - (NFRAG2_LOC + NFRAG2_VAL);
            bool isloc = rel < NFRAG1;
            if (!isloc) rel -= NFRAG1;
            int lane = rel & 31;
            int tn = rel >> 5;                          // 0..12
            int k0 = 2 * (lane & 3);
            int n  = tn * 8 + (lane >> 2);              // hidden unit j
            const float* Wm = isloc ? L1 : W1;
            const float* bm = isloc ? bl1 : b1;
            #pragma unroll
            for (int e = 0; e < 4; e++) {
                int k = k0 + (e >> 1) * 8 + (e & 1);
                float x = 0.0f;
                if (n < HID) {
                    if (k < SD)       x = Wm[k * HID + n];
                    else if (k == SD) x = bm[n];        // layer1 bias via s ones-col
                }
                v[e] = x;
            }
        }
        unsigned short hb[4], lb[4];
        #pragma unroll
        for (int e = 0; e < 4; e++) {
            __nv_bfloat16 h = __float2bfloat16(v[e]);
            hb[e] = __bfloat16_as_ushort(h);
            lb[e] = __bfloat16_as_ushort(__float2bfloat16(v[e] - __bfloat162float(h)));
        }
        uint4 o;
        o.x = (uint32_t)hb[0] | ((uint32_t)hb[1] << 16);
        o.y = (uint32_t)hb[2] | ((uint32_t)hb[3] << 16);
        o.z = (uint32_t)lb[0] | ((uint32_t)lb[1] << 16);
        o.w = (uint32_t)lb[2] | ((uint32_t)lb[3] << 16);
        d_bfrag[idx] = o;
    }
}

// one branch, 16 rows/warp: layer1 (tensor) -> register relu/split -> layer2
template<int NT>
__device__ __forceinline__ void branch_gemm(
    const uint4* __restrict__ bf1, const uint4* __restrict__ bf2,
    const uint32_t (&Ash)[4], const uint32_t (&Asl)[4],
    int lane, int lq, float (&c)[NT][4])
{
    #pragma unroll
    for (int tn = 0; tn < NT; tn++)
        #pragma unroll
        for (int e = 0; e < 4; e++) c[tn][e] = 0.0f;

    #pragma unroll
    for (int q = 0; q < 7; q++) {
        // ---- layer1: hidden cols [16q, 16q+16) ----
        float C[2][4];
        #pragma unroll
        for (int h = 0; h < 2; h++)
            #pragma unroll
            for (int e = 0; e < 4; e++) C[h][e] = 0.0f;

        #pragma unroll
        for (int nt2 = 0; nt2 < 2; nt2++) {
            const int tn = 2 * q + nt2;
            if (tn < 13) {
                uint4 b = __ldg(&bf1[tn * 32 + lane]);
                mma_bf16(C[nt2], Ash, b.x, b.y);   // hi*hi
                mma_bf16(C[nt2], Ash, b.z, b.w);   // hi*lo
                mma_bf16(C[nt2], Asl, b.x, b.y);   // lo*hi
            }
        }
        // ---- relu + split -> layer2 A fragments (registers only) ----
        uint32_t Ah[4], Al[4];
        #pragma unroll
        for (int h = 0; h < 2; h++) {
            float v0 = fmaxf(C[h][0], 0.0f);
            float v1 = fmaxf(C[h][1], 0.0f);
            float v2 = fmaxf(C[h][2], 0.0f);
            float v3 = fmaxf(C[h][3], 0.0f);
            if (q == 6) {                  // cols 96..111: ones col @100, rest 0
                if (h == 0) {
                    if (lq == 2) { v0 = 1.0f; v2 = 1.0f; }
                } else {
                    v0 = v1 = v2 = v3 = 0.0f;
                }
            }
            split2(v0, v1, Ah[2 * h + 0], Al[2 * h + 0]);   // row lr
            split2(v2, v3, Ah[2 * h + 1], Al[2 * h + 1]);   // row lr+8
        }
        // ---- layer2 ----
        const uint4* bq = bf2 + q * NT * 32 + lane;
        #pragma unroll
        for (int tn = 0; tn < NT; tn++) {
            uint4 b = __ldg(&bq[tn * 32]);
            mma_bf16(c[tn], Ah, b.x, b.y);
            mma_bf16(c[tn], Ah, b.z, b.w);
            mma_bf16(c[tn], Al, b.x, b.y);
        }
    }
}

extern "C" __global__ void __launch_bounds__(THREADS, 6)
net_kernel(const float* __restrict__ s, const float* __restrict__ a,
           float* __restrict__ out, int B)
{
    const int t = threadIdx.x;
    const int lane = t & 31;
    const int warp = t >> 5;
    const int lq = lane & 3, lr = lane >> 2;

    const int base = blockIdx.x * 64 + warp * 16;

    // ---- A fragments of s (K=16: 10 inputs + ones col @10 for l1 bias) ----
    uint32_t Ash[4], Asl[4];
    #pragma unroll
    for (int rr = 0; rr < 2; rr++) {              // rr 0: row lr, 1: row lr+8
        int r = base + lr + rr * 8;
        r = r < B ? r : B - 1;
        const float* sr = s + (size_t)r * SD;
        float2 v01 = *(const float2*)(sr + 2 * lq);       // cols 2lq, 2lq+1
        float2 v23;                                       // cols 8+2lq, 9+2lq
        if (lq == 0)      v23 = *(const float2*)(sr + 8);
        else if (lq == 1) v23 = make_float2(1.0f, 0.0f);  // ones col @10
        else              v23 = make_float2(0.0f, 0.0f);
        split2(v01.x, v01.y, Ash[rr],     Asl[rr]);
        split2(v23.x, v23.y, Ash[2 + rr], Asl[2 + rr]);
    }

    const uint4* bf2_loc = d_bfrag;
    const uint4* bf2_val = d_bfrag + NFRAG2_LOC;
    const uint4* bf1_loc = d_bfrag + NFRAG2_LOC + NFRAG2_VAL;
    const uint4* bf1_val = bf1_loc + NFRAG1;

    // ---- loc branch: 30 centroid (x,y) pairs in N=64 ----
    float cl[8][4];
    branch_gemm<8>(bf1_loc, bf2_loc, Ash, Asl, lane, lq, cl);

    float2 av0, av1;
    { int r = base + lr;     r = r < B ? r : B - 1; av0 = *(const float2*)(a + (size_t)r * 2); }
    { int r = base + lr + 8; r = r < B ? r : B - 1; av1 = *(const float2*)(a + (size_t)r * 2); }

    // ---- loc epilogue: centroids -> ew (REGISTERS, no SMEM relay) + den ----
    float ew0[8], ew1[8];
    float den0 = 0.0f, den1 = 0.0f;
    #pragma unroll
    for (int tn = 0; tn < 8; tn++) {
        int n = tn * 4 + lq;
        float e0 = 0.0f, e1 = 0.0f;
        if (n < NC) {
            float px = MAXA_F * tanh_fast(cl[tn][0]);
            float py = MAXA_F * tanh_fast(cl[tn][1]);
            float dx = px - av0.x, dy = py - av0.y;
            e0 = __expf(-BETA_F * sqrtf(fmaf(dx, dx, dy * dy)));
            px = MAXA_F * tanh_fast(cl[tn][2]);
            py = MAXA_F * tanh_fast(cl[tn][3]);
            dx = px - av1.x; dy = py - av1.y;
            e1 = __expf(-BETA_F * sqrtf(fmaf(dx, dx, dy * dy)));
        }
        ew0[tn] = e0;
        ew1[tn] = e1;
        den0 += e0;
        den1 += e1;
    }
    den0 += __shfl_xor_sync(0xFFFFFFFFu, den0, 1);
    den0 += __shfl_xor_sync(0xFFFFFFFFu, den0, 2);
    den1 += __shfl_xor_sync(0xFFFFFFFFu, den1, 1);
    den1 += __shfl_xor_sync(0xFFFFFFFFu, den1, 2);

    // ---- val branch: 30 values in N=32, columns pre-permuted so that
    //      cv[tv][e]   = value of centroid n = 4*(2tv+e)+lq   (row lr)
    //      cv[tv][2+e] = same centroid, row lr+8
    float cv[4][4];
    branch_gemm<4>(bf1_val, bf2_val, Ash, Asl, lane, lq, cv);

    // ---- val epilogue: num = sum ew*v, all in registers ----
    float num0 = 0.0f, num1 = 0.0f;
    #pragma unroll
    for (int tv = 0; tv < 4; tv++) {
        num0 += ew0[2 * tv] * cv[tv][0] + ew0[2 * tv + 1] * cv[tv][1];
        num1 += ew1[2 * tv] * cv[tv][2] + ew1[2 * tv + 1] * cv[tv][3];
    }
    num0 += __shfl_xor_sync(0xFFFFFFFFu, num0, 1);
    num0 += __shfl_xor_sync(0xFFFFFFFFu, num0, 2);
    num1 += __shfl_xor_sync(0xFFFFFFFFu, num1, 1);
    num1 += __shfl_xor_sync(0xFFFFFFFFu, num1, 2);
    if (lq == 0) {
        int r0 = base + lr, r1 = base + lr + 8;
        if (r0 < B) out[r0] = num0 / den0;
        if (r1 < B) out[r1] = num1 / den1;
    }
}

extern "C" void kernel_launch(void* const* d_in, const int* in_sizes, int n_in,
                              void* d_out, int out_size) {
    const float* s   = (const float*)d_in[0];
    const float* a   = (const float*)d_in[1];
    const float* W1  = (const float*)d_in[2];
    const float* b1  = (const float*)d_in[3];
    const float* W2  = (const float*)d_in[4];
    const float* b2  = (const float*)d_in[5];
    const float* L1  = (const float*)d_in[6];
    const float* bl1 = (const float*)d_in[7];
    const float* WL2 = (const float*)d_in[8];
    const float* bL2 = (const float*)d_in[9];
    float* out = (float*)d_out;

    const int B = in_sizes[0] / SD;
    const int blocks = (B + 63) / 64;

    prep_kernel<<<8, 256>>>(W1, b1, W2, b2, L1, bl1, WL2, bL2);

    net_kernel<<<blocks, THREADS>>>(s, a, out, B);
}